// round 1
// baseline (speedup 1.0000x reference)
#include <cuda_runtime.h>
#include <math_constants.h>

#define N_NODES 50000
#define N_EDGES 800000
#define DIM 64

// ---- device scratch (no allocations allowed) ----
__device__ int   g_counts[N_NODES];
__device__ int   g_offsets[N_NODES + 1];
__device__ int   g_cursor[N_NODES];
__device__ int   g_srcidx[N_EDGES];
__device__ float g_x [N_NODES * DIM];   // (1+eps)*h + agg, input to GEMM
__device__ float g_h0[N_NODES * DIM];   // h after layer 0
__device__ float g_h1[N_NODES * DIM];   // h after layer 1

// ---------------- CSR build ----------------

__global__ void k_zero_counts() {
    int i = blockIdx.x * blockDim.x + threadIdx.x;
    if (i < N_NODES) g_counts[i] = 0;
}

__global__ void k_count(const int* __restrict__ dst) {
    int i = blockIdx.x * blockDim.x + threadIdx.x;
    if (i < N_EDGES) atomicAdd(&g_counts[dst[i]], 1);
}

// single-block exclusive scan of g_counts -> g_offsets (+ copy to g_cursor)
__global__ void k_scan() {
    __shared__ int warp_sums[32];
    __shared__ int carry_s;
    int t = threadIdx.x, lane = t & 31, wid = t >> 5;
    if (t == 0) carry_s = 0;
    __syncthreads();
    for (int base = 0; base < N_NODES; base += 1024) {
        int i = base + t;
        int v = (i < N_NODES) ? g_counts[i] : 0;
        int s = v;
        #pragma unroll
        for (int d = 1; d < 32; d <<= 1) {
            int y = __shfl_up_sync(0xffffffffu, s, d);
            if (lane >= d) s += y;
        }
        if (lane == 31) warp_sums[wid] = s;
        __syncthreads();
        if (wid == 0) {
            int ws = warp_sums[lane];
            #pragma unroll
            for (int d = 1; d < 32; d <<= 1) {
                int y = __shfl_up_sync(0xffffffffu, ws, d);
                if (lane >= d) ws += y;
            }
            warp_sums[lane] = ws;
        }
        __syncthreads();
        int carry_now = carry_s;
        int excl = s - v + (wid > 0 ? warp_sums[wid - 1] : 0) + carry_now;
        if (i < N_NODES) { g_offsets[i] = excl; g_cursor[i] = excl; }
        __syncthreads();
        if (t == 1023) carry_s = warp_sums[31] + carry_now;
        __syncthreads();
    }
    if (t == 0) g_offsets[N_NODES] = carry_s;
}

__global__ void k_scatter(const int* __restrict__ src, const int* __restrict__ dst) {
    int i = blockIdx.x * blockDim.x + threadIdx.x;
    if (i < N_EDGES) {
        int d = dst[i];
        int pos = atomicAdd(&g_cursor[d], 1);
        g_srcidx[pos] = src[i];
    }
}

// ---------------- per-layer aggregation ----------------
// warp per node: segment-max over incoming edges, then x = (1+eps)*h + agg
__global__ void k_agg(const float* __restrict__ h,
                      const float* __restrict__ eps, int layer,
                      float* __restrict__ x) {
    int warp = (blockIdx.x * blockDim.x + threadIdx.x) >> 5;
    int lane = threadIdx.x & 31;
    if (warp >= N_NODES) return;

    int beg = g_offsets[warp];
    int end = g_offsets[warp + 1];

    float m0 = -CUDART_INF_F, m1 = -CUDART_INF_F;
    int i = beg;
    for (; i + 4 <= end; i += 4) {
        int s0 = __ldg(&g_srcidx[i + 0]);
        int s1 = __ldg(&g_srcidx[i + 1]);
        int s2 = __ldg(&g_srcidx[i + 2]);
        int s3 = __ldg(&g_srcidx[i + 3]);
        const float* r0 = h + (size_t)s0 * DIM;
        const float* r1 = h + (size_t)s1 * DIM;
        const float* r2 = h + (size_t)s2 * DIM;
        const float* r3 = h + (size_t)s3 * DIM;
        float a0 = __ldg(r0 + lane),      a1 = __ldg(r1 + lane);
        float a2 = __ldg(r2 + lane),      a3 = __ldg(r3 + lane);
        float c0 = __ldg(r0 + 32 + lane), c1 = __ldg(r1 + 32 + lane);
        float c2 = __ldg(r2 + 32 + lane), c3 = __ldg(r3 + 32 + lane);
        m0 = fmaxf(m0, fmaxf(fmaxf(a0, a1), fmaxf(a2, a3)));
        m1 = fmaxf(m1, fmaxf(fmaxf(c0, c1), fmaxf(c2, c3)));
    }
    for (; i < end; ++i) {
        int s = __ldg(&g_srcidx[i]);
        const float* r = h + (size_t)s * DIM;
        m0 = fmaxf(m0, __ldg(r + lane));
        m1 = fmaxf(m1, __ldg(r + 32 + lane));
    }
    if (beg == end) { m0 = 0.0f; m1 = 0.0f; }  // DGL: zero-fill for no in-edges

    float ep = 1.0f + __ldg(eps + layer);
    size_t rowo = (size_t)warp * DIM;
    x[rowo + lane]      = fmaf(ep, __ldg(h + rowo + lane),      m0);
    x[rowo + 32 + lane] = fmaf(ep, __ldg(h + rowo + 32 + lane), m1);
}

// ---------------- GEMM: out[n] = x[n] @ W + b, optional leaky-relu ----------------
// block = 256 threads, tile = 64 nodes. 4x4 register blocking.
__global__ void k_gemm(const float* __restrict__ x,
                       const float* __restrict__ W,
                       const float* __restrict__ bias,
                       float* __restrict__ out,
                       int activate) {
    __shared__ float Ws[64 * 64];      // row-major [k][j]
    __shared__ float Xs[64 * 68];      // padded stride 68 (bank-conflict-free)

    int t = threadIdx.x;               // 0..255
    int base = blockIdx.x * 64;

    // load W (4096 floats) via float4
    const float4* W4 = (const float4*)W;
    float4* Ws4 = (float4*)Ws;
    #pragma unroll
    for (int p = 0; p < 4; p++) Ws4[t + p * 256] = W4[t + p * 256];

    // load X tile (64 nodes x 64) via float4 into padded smem
    const float4* X4 = (const float4*)(x + (size_t)base * DIM);
    #pragma unroll
    for (int p = 0; p < 4; p++) {
        int idx = t + p * 256;         // float4 index: node = idx>>4, chunk = idx&15
        int n = idx >> 4, c = idx & 15;
        float4 v = make_float4(0.f, 0.f, 0.f, 0.f);
        if (base + n < N_NODES) v = X4[idx];
        *(float4*)&Xs[n * 68 + c * 4] = v;
    }
    __syncthreads();

    int jg = t & 15;    // output column group: j = jg*4 .. +3
    int ng = t >> 4;    // node group: n = ng*4 .. +3

    float acc[4][4];
    float4 bj = *(const float4*)(bias + jg * 4);
    #pragma unroll
    for (int i = 0; i < 4; i++) {
        acc[i][0] = bj.x; acc[i][1] = bj.y; acc[i][2] = bj.z; acc[i][3] = bj.w;
    }

    #pragma unroll
    for (int k = 0; k < 64; k++) {
        float4 w = *(const float4*)&Ws[k * 64 + jg * 4];
        float xv[4];
        #pragma unroll
        for (int i = 0; i < 4; i++) xv[i] = Xs[(ng * 4 + i) * 68 + k];
        #pragma unroll
        for (int i = 0; i < 4; i++) {
            acc[i][0] = fmaf(xv[i], w.x, acc[i][0]);
            acc[i][1] = fmaf(xv[i], w.y, acc[i][1]);
            acc[i][2] = fmaf(xv[i], w.z, acc[i][2]);
            acc[i][3] = fmaf(xv[i], w.w, acc[i][3]);
        }
    }

    #pragma unroll
    for (int i = 0; i < 4; i++) {
        int n = base + ng * 4 + i;
        if (n < N_NODES) {
            float4 v;
            v.x = acc[i][0]; v.y = acc[i][1]; v.z = acc[i][2]; v.w = acc[i][3];
            if (activate) {
                v.x = v.x >= 0.f ? v.x : 0.01f * v.x;
                v.y = v.y >= 0.f ? v.y : 0.01f * v.y;
                v.z = v.z >= 0.f ? v.z : 0.01f * v.z;
                v.w = v.w >= 0.f ? v.w : 0.01f * v.w;
            }
            *(float4*)&out[(size_t)n * DIM + jg * 4] = v;
        }
    }
}

// ---------------- launch ----------------
extern "C" void kernel_launch(void* const* d_in, const int* in_sizes, int n_in,
                              void* d_out, int out_size) {
    const float* n_feat = (const float*)d_in[0];
    const float* W0 = (const float*)d_in[1];
    const float* b0 = (const float*)d_in[2];
    const float* W1 = (const float*)d_in[3];
    const float* b1 = (const float*)d_in[4];
    const float* W2 = (const float*)d_in[5];
    const float* b2 = (const float*)d_in[6];
    const float* eps = (const float*)d_in[7];
    const int*   src = (const int*)d_in[8];
    const int*   dst = (const int*)d_in[9];
    float* out = (float*)d_out;

    float *x_ptr, *h0_ptr, *h1_ptr;
    cudaGetSymbolAddress((void**)&x_ptr,  g_x);
    cudaGetSymbolAddress((void**)&h0_ptr, g_h0);
    cudaGetSymbolAddress((void**)&h1_ptr, g_h1);

    // CSR build (graph identical across all 3 layers)
    k_zero_counts<<<(N_NODES + 255) / 256, 256>>>();
    k_count<<<(N_EDGES + 255) / 256, 256>>>(dst);
    k_scan<<<1, 1024>>>();
    k_scatter<<<(N_EDGES + 255) / 256, 256>>>(src, dst);

    const int agg_blocks  = (N_NODES * 32 + 255) / 256;
    const int gemm_blocks = (N_NODES + 63) / 64;

    // layer 0
    k_agg <<<agg_blocks, 256>>>(n_feat, eps, 0, x_ptr);
    k_gemm<<<gemm_blocks, 256>>>(x_ptr, W0, b0, h0_ptr, 1);
    // layer 1
    k_agg <<<agg_blocks, 256>>>(h0_ptr, eps, 1, x_ptr);
    k_gemm<<<gemm_blocks, 256>>>(x_ptr, W1, b1, h1_ptr, 1);
    // layer 2 (no activation)
    k_agg <<<agg_blocks, 256>>>(h1_ptr, eps, 2, x_ptr);
    k_gemm<<<gemm_blocks, 256>>>(x_ptr, W2, b2, out, 0);
}

// round 2
// speedup vs baseline: 1.1271x; 1.1271x over previous
#include <cuda_runtime.h>
#include <math_constants.h>

#define N_NODES 50000
#define N_EDGES 800000
#define DIM 64
#define SCAN_BLOCKS 196   // 196*256 = 50176 >= 50000

// ---- device scratch (no allocations allowed) ----
__device__ int   g_counts[N_NODES];
__device__ int   g_offsets[N_NODES + 1];
__device__ int   g_cursor[N_NODES];
__device__ int   g_bsum[SCAN_BLOCKS];
__device__ int   g_srcidx[N_EDGES];
__device__ float g_h0[N_NODES * DIM];
__device__ float g_h1[N_NODES * DIM];

// ---------------- CSR build ----------------

__global__ void k_zero_counts() {
    int i = blockIdx.x * blockDim.x + threadIdx.x;
    if (i < N_NODES) g_counts[i] = 0;
}

// 4 edges per thread via int4
__global__ void k_count(const int* __restrict__ dst) {
    int i = blockIdx.x * blockDim.x + threadIdx.x;
    if (i < N_EDGES / 4) {
        int4 d = __ldg((const int4*)dst + i);
        atomicAdd(&g_counts[d.x], 1);
        atomicAdd(&g_counts[d.y], 1);
        atomicAdd(&g_counts[d.z], 1);
        atomicAdd(&g_counts[d.w], 1);
    }
}

// multi-block scan, pass 1: per-block exclusive scan + block sums
__global__ void k_scan1() {
    __shared__ int warp_sums[8];
    int t = threadIdx.x, lane = t & 31, wid = t >> 5;
    int i = blockIdx.x * 256 + t;
    int v = (i < N_NODES) ? g_counts[i] : 0;
    int s = v;
    #pragma unroll
    for (int d = 1; d < 32; d <<= 1) {
        int y = __shfl_up_sync(0xffffffffu, s, d);
        if (lane >= d) s += y;
    }
    if (lane == 31) warp_sums[wid] = s;
    __syncthreads();
    if (wid == 0 && lane < 8) {
        int ws = warp_sums[lane];
        #pragma unroll
        for (int d = 1; d < 8; d <<= 1) {
            int y = __shfl_up_sync(0xffu, ws, d);
            if (lane >= d) ws += y;
        }
        warp_sums[lane] = ws;
    }
    __syncthreads();
    int excl = s - v + (wid > 0 ? warp_sums[wid - 1] : 0);
    if (i < N_NODES) g_offsets[i] = excl;
    if (t == 255) g_bsum[blockIdx.x] = excl + v;
}

// pass 2: single block scans the 196 block sums (exclusive in place)
__global__ void k_scan2() {
    __shared__ int warp_sums[8];
    int t = threadIdx.x, lane = t & 31, wid = t >> 5;
    int v = (t < SCAN_BLOCKS) ? g_bsum[t] : 0;
    int s = v;
    #pragma unroll
    for (int d = 1; d < 32; d <<= 1) {
        int y = __shfl_up_sync(0xffffffffu, s, d);
        if (lane >= d) s += y;
    }
    if (lane == 31) warp_sums[wid] = s;
    __syncthreads();
    if (wid == 0 && lane < 8) {
        int ws = warp_sums[lane];
        #pragma unroll
        for (int d = 1; d < 8; d <<= 1) {
            int y = __shfl_up_sync(0xffu, ws, d);
            if (lane >= d) ws += y;
        }
        warp_sums[lane] = ws;
    }
    __syncthreads();
    int incl = s + (wid > 0 ? warp_sums[wid - 1] : 0);
    if (t < SCAN_BLOCKS) g_bsum[t] = incl - v;
    if (t == SCAN_BLOCKS - 1) g_offsets[N_NODES] = incl;  // total edges
}

// pass 3: add block prefix, also fill cursor
__global__ void k_scan3() {
    int i = blockIdx.x * 256 + threadIdx.x;
    if (i < N_NODES) {
        int o = g_offsets[i] + g_bsum[blockIdx.x];
        g_offsets[i] = o;
        g_cursor[i]  = o;
    }
}

// 4 edges per thread via int4
__global__ void k_scatter(const int* __restrict__ src, const int* __restrict__ dst) {
    int i = blockIdx.x * blockDim.x + threadIdx.x;
    if (i < N_EDGES / 4) {
        int4 s = __ldg((const int4*)src + i);
        int4 d = __ldg((const int4*)dst + i);
        g_srcidx[atomicAdd(&g_cursor[d.x], 1)] = s.x;
        g_srcidx[atomicAdd(&g_cursor[d.y], 1)] = s.y;
        g_srcidx[atomicAdd(&g_cursor[d.z], 1)] = s.z;
        g_srcidx[atomicAdd(&g_cursor[d.w], 1)] = s.w;
    }
}

// ---------------- fused layer: agg (segment-max) + GEMM + bias + leaky-relu ----
// block = 512 threads (16 warps), tile = 64 nodes.
// Phase 1: each warp aggregates 4 nodes into smem X tile (float2 per lane).
// Phase 2: block GEMM 64x64x64 with W in smem, 2x4 register blocking.
__global__ void __launch_bounds__(512) k_layer(
        const float* __restrict__ h,
        const float* __restrict__ W,
        const float* __restrict__ bias,
        const float* __restrict__ eps, int layer,
        float* __restrict__ out, int activate) {
    __shared__ float Ws[64 * 64];     // [k][j]
    __shared__ float Xs[64 * 68];     // padded stride 68

    int t = threadIdx.x;              // 0..511
    int base = blockIdx.x * 64;

    // load W via float4 (1024 float4 over 512 threads)
    const float4* W4 = (const float4*)W;
    float4* Ws4 = (float4*)Ws;
    Ws4[t]       = W4[t];
    Ws4[t + 512] = W4[t + 512];

    float ep = 1.0f + __ldg(eps + layer);
    int warp = t >> 5, lane = t & 31;

    // ---- phase 1: aggregation, warp handles 4 nodes ----
    #pragma unroll
    for (int q = 0; q < 4; q++) {
        int nl = warp * 4 + q;        // local node 0..63
        int n = base + nl;
        if (n < N_NODES) {
            int beg = g_offsets[n];
            int end = g_offsets[n + 1];
            float m0 = -CUDART_INF_F, m1 = -CUDART_INF_F;
            int i = beg;
            for (; i + 4 <= end; i += 4) {
                int s0 = __ldg(&g_srcidx[i + 0]);
                int s1 = __ldg(&g_srcidx[i + 1]);
                int s2 = __ldg(&g_srcidx[i + 2]);
                int s3 = __ldg(&g_srcidx[i + 3]);
                float2 a0 = __ldg((const float2*)(h + (size_t)s0 * DIM) + lane);
                float2 a1 = __ldg((const float2*)(h + (size_t)s1 * DIM) + lane);
                float2 a2 = __ldg((const float2*)(h + (size_t)s2 * DIM) + lane);
                float2 a3 = __ldg((const float2*)(h + (size_t)s3 * DIM) + lane);
                m0 = fmaxf(m0, fmaxf(fmaxf(a0.x, a1.x), fmaxf(a2.x, a3.x)));
                m1 = fmaxf(m1, fmaxf(fmaxf(a0.y, a1.y), fmaxf(a2.y, a3.y)));
            }
            for (; i < end; ++i) {
                int s = __ldg(&g_srcidx[i]);
                float2 a = __ldg((const float2*)(h + (size_t)s * DIM) + lane);
                m0 = fmaxf(m0, a.x);
                m1 = fmaxf(m1, a.y);
            }
            if (beg == end) { m0 = 0.0f; m1 = 0.0f; }   // DGL zero-fill
            float2 hs = __ldg((const float2*)(h + (size_t)n * DIM) + lane);
            float2 xv;
            xv.x = fmaf(ep, hs.x, m0);
            xv.y = fmaf(ep, hs.y, m1);
            *(float2*)&Xs[nl * 68 + lane * 2] = xv;
        }
    }
    __syncthreads();

    // ---- phase 2: GEMM out[64x64] = Xs @ Ws + b ----
    int jg = t & 15;                  // column group (4 cols)
    int ng = t >> 4;                  // node group (2 nodes), 0..31

    float acc[2][4];
    float4 bj = *(const float4*)(bias + jg * 4);
    #pragma unroll
    for (int i = 0; i < 2; i++) {
        acc[i][0] = bj.x; acc[i][1] = bj.y; acc[i][2] = bj.z; acc[i][3] = bj.w;
    }

    #pragma unroll
    for (int k = 0; k < 64; k++) {
        float4 w = *(const float4*)&Ws[k * 64 + jg * 4];
        float x0 = Xs[(ng * 2 + 0) * 68 + k];
        float x1 = Xs[(ng * 2 + 1) * 68 + k];
        acc[0][0] = fmaf(x0, w.x, acc[0][0]);
        acc[0][1] = fmaf(x0, w.y, acc[0][1]);
        acc[0][2] = fmaf(x0, w.z, acc[0][2]);
        acc[0][3] = fmaf(x0, w.w, acc[0][3]);
        acc[1][0] = fmaf(x1, w.x, acc[1][0]);
        acc[1][1] = fmaf(x1, w.y, acc[1][1]);
        acc[1][2] = fmaf(x1, w.z, acc[1][2]);
        acc[1][3] = fmaf(x1, w.w, acc[1][3]);
    }

    #pragma unroll
    for (int i = 0; i < 2; i++) {
        int n = base + ng * 2 + i;
        if (n < N_NODES) {
            float4 v;
            v.x = acc[i][0]; v.y = acc[i][1]; v.z = acc[i][2]; v.w = acc[i][3];
            if (activate) {
                v.x = v.x >= 0.f ? v.x : 0.01f * v.x;
                v.y = v.y >= 0.f ? v.y : 0.01f * v.y;
                v.z = v.z >= 0.f ? v.z : 0.01f * v.z;
                v.w = v.w >= 0.f ? v.w : 0.01f * v.w;
            }
            *(float4*)&out[(size_t)n * DIM + jg * 4] = v;
        }
    }
}

// ---------------- launch ----------------
extern "C" void kernel_launch(void* const* d_in, const int* in_sizes, int n_in,
                              void* d_out, int out_size) {
    const float* n_feat = (const float*)d_in[0];
    const float* W0 = (const float*)d_in[1];
    const float* b0 = (const float*)d_in[2];
    const float* W1 = (const float*)d_in[3];
    const float* b1 = (const float*)d_in[4];
    const float* W2 = (const float*)d_in[5];
    const float* b2 = (const float*)d_in[6];
    const float* eps = (const float*)d_in[7];
    const int*   src = (const int*)d_in[8];
    const int*   dst = (const int*)d_in[9];
    float* out = (float*)d_out;

    float *h0_ptr, *h1_ptr;
    cudaGetSymbolAddress((void**)&h0_ptr, g_h0);
    cudaGetSymbolAddress((void**)&h1_ptr, g_h1);

    // CSR build
    k_zero_counts<<<(N_NODES + 511) / 512, 512>>>();
    k_count<<<(N_EDGES / 4 + 255) / 256, 256>>>(dst);
    k_scan1<<<SCAN_BLOCKS, 256>>>();
    k_scan2<<<1, 256>>>();
    k_scan3<<<SCAN_BLOCKS, 256>>>();
    k_scatter<<<(N_EDGES / 4 + 255) / 256, 256>>>(src, dst);

    const int layer_blocks = (N_NODES + 63) / 64;   // 782

    k_layer<<<layer_blocks, 512>>>(n_feat, W0, b0, eps, 0, h0_ptr, 1);
    k_layer<<<layer_blocks, 512>>>(h0_ptr, W1, b1, eps, 1, h1_ptr, 1);
    k_layer<<<layer_blocks, 512>>>(h1_ptr, W2, b2, eps, 2, out, 0);
}

// round 3
// speedup vs baseline: 1.1482x; 1.0187x over previous
#include <cuda_runtime.h>
#include <math_constants.h>

#define N_NODES 50000
#define N_EDGES 800000
#define DIM 64
#define SCAN_BLOCKS 196   // 196*256 = 50176 >= 50000

// ---- device scratch (no allocations allowed; static zero-init) ----
__device__ int   g_counts[N_NODES];      // zeroed at end of every launch sequence
__device__ int   g_offsets[N_NODES + 1];
__device__ int   g_cursor[N_NODES];
__device__ int   g_bsum[SCAN_BLOCKS];
__device__ int   g_srcidx[N_EDGES];
__device__ float g_h0[N_NODES * DIM];
__device__ float g_h1[N_NODES * DIM];

// ---------------- CSR build ----------------

// 4 edges per thread via int4 (counts pre-zeroed by previous call / static init)
__global__ void k_count(const int* __restrict__ dst) {
    int i = blockIdx.x * blockDim.x + threadIdx.x;
    if (i < N_EDGES / 4) {
        int4 d = __ldg((const int4*)dst + i);
        atomicAdd(&g_counts[d.x], 1);
        atomicAdd(&g_counts[d.y], 1);
        atomicAdd(&g_counts[d.z], 1);
        atomicAdd(&g_counts[d.w], 1);
    }
}

// pass 1: per-block exclusive scan + block sums
__global__ void k_scan1() {
    __shared__ int warp_sums[8];
    int t = threadIdx.x, lane = t & 31, wid = t >> 5;
    int i = blockIdx.x * 256 + t;
    int v = (i < N_NODES) ? g_counts[i] : 0;
    int s = v;
    #pragma unroll
    for (int d = 1; d < 32; d <<= 1) {
        int y = __shfl_up_sync(0xffffffffu, s, d);
        if (lane >= d) s += y;
    }
    if (lane == 31) warp_sums[wid] = s;
    __syncthreads();
    if (wid == 0 && lane < 8) {
        int ws = warp_sums[lane];
        #pragma unroll
        for (int d = 1; d < 8; d <<= 1) {
            int y = __shfl_up_sync(0xffu, ws, d);
            if (lane >= d) ws += y;
        }
        warp_sums[lane] = ws;
    }
    __syncthreads();
    int excl = s - v + (wid > 0 ? warp_sums[wid - 1] : 0);
    if (i < N_NODES) g_offsets[i] = excl;
    if (t == 255) g_bsum[blockIdx.x] = excl + v;
}

// pass 2 (merged old scan2+scan3): each block computes its own block-prefix
// by direct summation of g_bsum[0..b) with one warp, applies it, fills the
// cursor, and resets g_counts for the next invocation.
__global__ void k_scan23() {
    __shared__ int prefix_s;
    int t = threadIdx.x;
    int b = blockIdx.x;
    if (t < 32) {
        int acc = 0;
        for (int j = t; j < b; j += 32) acc += g_bsum[j];   // <= 7 iters
        #pragma unroll
        for (int d = 16; d > 0; d >>= 1) acc += __shfl_down_sync(0xffffffffu, acc, d);
        if (t == 0) prefix_s = acc;
    }
    __syncthreads();
    int prefix = prefix_s;
    int i = b * 256 + t;
    if (i < N_NODES) {
        int o = g_offsets[i] + prefix;
        g_offsets[i] = o;
        g_cursor[i]  = o;
        g_counts[i]  = 0;            // reset for next graph replay
    }
    if (b == SCAN_BLOCKS - 1 && t == 0)
        g_offsets[N_NODES] = prefix + g_bsum[b];
}

// 4 edges per thread via int4
__global__ void k_scatter(const int* __restrict__ src, const int* __restrict__ dst) {
    int i = blockIdx.x * blockDim.x + threadIdx.x;
    if (i < N_EDGES / 4) {
        int4 s = __ldg((const int4*)src + i);
        int4 d = __ldg((const int4*)dst + i);
        g_srcidx[atomicAdd(&g_cursor[d.x], 1)] = s.x;
        g_srcidx[atomicAdd(&g_cursor[d.y], 1)] = s.y;
        g_srcidx[atomicAdd(&g_cursor[d.z], 1)] = s.z;
        g_srcidx[atomicAdd(&g_cursor[d.w], 1)] = s.w;
    }
}

// ---------------- fused layer: agg (segment-max) + GEMM + bias + leaky-relu ----
__global__ void __launch_bounds__(512) k_layer(
        const float* __restrict__ h,
        const float* __restrict__ W,
        const float* __restrict__ bias,
        const float* __restrict__ eps, int layer,
        float* __restrict__ out, int activate) {
    __shared__ float Ws[64 * 64];     // [k][j]
    __shared__ float Xs[64 * 68];     // padded stride 68

    int t = threadIdx.x;              // 0..511
    int base = blockIdx.x * 64;

    // load W via float4 (1024 float4 over 512 threads)
    const float4* W4 = (const float4*)W;
    float4* Ws4 = (float4*)Ws;
    Ws4[t]       = W4[t];
    Ws4[t + 512] = W4[t + 512];

    float ep = 1.0f + __ldg(eps + layer);
    int warp = t >> 5, lane = t & 31;

    // ---- phase 1: aggregation, warp handles 4 nodes, unroll 8 ----
    #pragma unroll
    for (int q = 0; q < 4; q++) {
        int nl = warp * 4 + q;
        int n = base + nl;
        if (n < N_NODES) {
            int beg = g_offsets[n];
            int end = g_offsets[n + 1];
            float m0 = -CUDART_INF_F, m1 = -CUDART_INF_F;
            int i = beg;
            for (; i + 8 <= end; i += 8) {
                int sx[8];
                #pragma unroll
                for (int u = 0; u < 8; u++) sx[u] = __ldg(&g_srcidx[i + u]);
                float2 a[8];
                #pragma unroll
                for (int u = 0; u < 8; u++)
                    a[u] = __ldg((const float2*)(h + (size_t)sx[u] * DIM) + lane);
                #pragma unroll
                for (int u = 0; u < 8; u++) {
                    m0 = fmaxf(m0, a[u].x);
                    m1 = fmaxf(m1, a[u].y);
                }
            }
            for (; i < end; ++i) {
                int s = __ldg(&g_srcidx[i]);
                float2 a = __ldg((const float2*)(h + (size_t)s * DIM) + lane);
                m0 = fmaxf(m0, a.x);
                m1 = fmaxf(m1, a.y);
            }
            if (beg == end) { m0 = 0.0f; m1 = 0.0f; }   // DGL zero-fill
            float2 hs = __ldg((const float2*)(h + (size_t)n * DIM) + lane);
            float2 xv;
            xv.x = fmaf(ep, hs.x, m0);
            xv.y = fmaf(ep, hs.y, m1);
            *(float2*)&Xs[nl * 68 + lane * 2] = xv;
        }
    }
    __syncthreads();

    // ---- phase 2: GEMM out[64x64] = Xs @ Ws + b ----
    int jg = t & 15;                  // column group (4 cols)
    int ng = t >> 4;                  // node group (2 nodes), 0..31

    float acc[2][4];
    float4 bj = *(const float4*)(bias + jg * 4);
    #pragma unroll
    for (int i = 0; i < 2; i++) {
        acc[i][0] = bj.x; acc[i][1] = bj.y; acc[i][2] = bj.z; acc[i][3] = bj.w;
    }

    #pragma unroll
    for (int k = 0; k < 64; k++) {
        float4 w = *(const float4*)&Ws[k * 64 + jg * 4];
        float x0 = Xs[(ng * 2 + 0) * 68 + k];
        float x1 = Xs[(ng * 2 + 1) * 68 + k];
        acc[0][0] = fmaf(x0, w.x, acc[0][0]);
        acc[0][1] = fmaf(x0, w.y, acc[0][1]);
        acc[0][2] = fmaf(x0, w.z, acc[0][2]);
        acc[0][3] = fmaf(x0, w.w, acc[0][3]);
        acc[1][0] = fmaf(x1, w.x, acc[1][0]);
        acc[1][1] = fmaf(x1, w.y, acc[1][1]);
        acc[1][2] = fmaf(x1, w.z, acc[1][2]);
        acc[1][3] = fmaf(x1, w.w, acc[1][3]);
    }

    #pragma unroll
    for (int i = 0; i < 2; i++) {
        int n = base + ng * 2 + i;
        if (n < N_NODES) {
            float4 v;
            v.x = acc[i][0]; v.y = acc[i][1]; v.z = acc[i][2]; v.w = acc[i][3];
            if (activate) {
                v.x = v.x >= 0.f ? v.x : 0.01f * v.x;
                v.y = v.y >= 0.f ? v.y : 0.01f * v.y;
                v.z = v.z >= 0.f ? v.z : 0.01f * v.z;
                v.w = v.w >= 0.f ? v.w : 0.01f * v.w;
            }
            *(float4*)&out[(size_t)n * DIM + jg * 4] = v;
        }
    }
}

// ---------------- launch ----------------
extern "C" void kernel_launch(void* const* d_in, const int* in_sizes, int n_in,
                              void* d_out, int out_size) {
    const float* n_feat = (const float*)d_in[0];
    const float* W0 = (const float*)d_in[1];
    const float* b0 = (const float*)d_in[2];
    const float* W1 = (const float*)d_in[3];
    const float* b1 = (const float*)d_in[4];
    const float* W2 = (const float*)d_in[5];
    const float* b2 = (const float*)d_in[6];
    const float* eps = (const float*)d_in[7];
    const int*   src = (const int*)d_in[8];
    const int*   dst = (const int*)d_in[9];
    float* out = (float*)d_out;

    float *h0_ptr, *h1_ptr;
    cudaGetSymbolAddress((void**)&h0_ptr, g_h0);
    cudaGetSymbolAddress((void**)&h1_ptr, g_h1);

    // CSR build (4 launches)
    k_count<<<(N_EDGES / 4 + 255) / 256, 256>>>(dst);
    k_scan1<<<SCAN_BLOCKS, 256>>>();
    k_scan23<<<SCAN_BLOCKS, 256>>>();
    k_scatter<<<(N_EDGES / 4 + 255) / 256, 256>>>(src, dst);

    const int layer_blocks = (N_NODES + 63) / 64;   // 782

    k_layer<<<layer_blocks, 512>>>(n_feat, W0, b0, eps, 0, h0_ptr, 1);
    k_layer<<<layer_blocks, 512>>>(h0_ptr, W1, b1, eps, 1, h1_ptr, 1);
    k_layer<<<layer_blocks, 512>>>(h1_ptr, W2, b2, eps, 2, out, 0);
}